// round 3
// baseline (speedup 1.0000x reference)
#include <cuda_runtime.h>
#include <math.h>

#define N_NODES 200000
#define N_EDGES 1250000
#define N_GRAPHS 2048
#define IN_CH 128
#define HID 64
#define EMB 32

// ---------------- scratch (static device globals; no allocation) ----------------
__device__ int   g_is64;                 // 1 if edge_index/batch are int64, else int32
__device__ int   g_deg[N_NODES];
__device__ float g_dis[N_NODES];
__device__ int   g_off[N_NODES];
__device__ int   g_cur[N_NODES];
__device__ int   g_csr[N_EDGES];
__device__ int   g_bsums[256];
__device__ __align__(16) float g_h1[(size_t)N_NODES * 64];   // GEMM output
__device__ __align__(16) float g_h2[(size_t)N_NODES * 64];   // AGG output / GEMM input

// Read logical element i of an index buffer whose dtype (int32/int64) is in g_is64.
__device__ __forceinline__ long long load_idx(const void* p, long long i, int is64) {
    if (is64) return ((const long long*)p)[i];
    return (long long)((const int*)p)[i];
}

// ---------------- dtype detector ----------------
// If values are int64 (nonnegative, < 2^31), odd 32-bit words are all zero.
__global__ void k_detect(const unsigned* __restrict__ ei_words) {
    __shared__ int any_nonzero;
    if (threadIdx.x == 0) any_nonzero = 0;
    __syncthreads();
    // check odd words across a spread of positions
    unsigned w = ei_words[2 * threadIdx.x + 1];
    if (w != 0u) atomicOr(&any_nonzero, 1);
    __syncthreads();
    if (threadIdx.x == 0) g_is64 = any_nonzero ? 0 : 1;
}

// ---------------- utility: block inclusive scan ----------------
template <int NT>
__device__ __forceinline__ int block_inclusive_scan(int v, int tid) {
    int lane = tid & 31, w = tid >> 5;
    int x = v;
#pragma unroll
    for (int o = 1; o < 32; o <<= 1) {
        int y = __shfl_up_sync(0xffffffffu, x, o);
        if (lane >= o) x += y;
    }
    __shared__ int wsum[NT / 32];
    if (lane == 31) wsum[w] = x;
    __syncthreads();
    if (w == 0) {
        const int NW = NT / 32;
        int s = (lane < NW) ? wsum[lane] : 0;
#pragma unroll
        for (int o = 1; o < 32; o <<= 1) {
            int y = __shfl_up_sync(0xffffffffu, s, o);
            if (lane >= o) s += y;
        }
        if (lane < NW) wsum[lane] = s;
    }
    __syncthreads();
    return x + (w ? wsum[w - 1] : 0);
}

// ---------------- graph preprocessing ----------------
__global__ void k_zero_deg() {
    int i = blockIdx.x * 1024 + threadIdx.x;
    if (i < N_NODES) g_deg[i] = 0;
}

__global__ void k_count_deg(const void* __restrict__ ei) {
    int e = blockIdx.x * 256 + threadIdx.x;
    int is64 = g_is64;
    if (e < N_EDGES) {
        int d = (int)load_idx(ei, (long long)N_EDGES + e, is64);  // dst
        if (d >= 0 && d < N_NODES) atomicAdd(&g_deg[d], 1);
    }
}

__global__ void k_scan1() {
    int idx = blockIdx.x * 1024 + threadIdx.x;
    int v = (idx < N_NODES) ? g_deg[idx] : 0;
    int incl = block_inclusive_scan<1024>(v, threadIdx.x);
    if (idx < N_NODES) g_off[idx] = incl - v;
    if (threadIdx.x == 1023) g_bsums[blockIdx.x] = incl;
}

__global__ void k_scan2(int nb) {
    int v = ((int)threadIdx.x < nb) ? g_bsums[threadIdx.x] : 0;
    int incl = block_inclusive_scan<256>(v, threadIdx.x);
    if ((int)threadIdx.x < nb) g_bsums[threadIdx.x] = incl - v;  // exclusive
}

__global__ void k_scan3() {
    int idx = blockIdx.x * 256 + threadIdx.x;
    if (idx < N_NODES) {
        int o = g_off[idx] + g_bsums[idx >> 10];
        g_off[idx] = o;
        g_cur[idx] = o;
        g_dis[idx] = rsqrtf(1.0f + (float)g_deg[idx]);
    }
}

__global__ void k_fill_csr(const void* __restrict__ ei) {
    int e = blockIdx.x * 256 + threadIdx.x;
    int is64 = g_is64;
    if (e < N_EDGES) {
        int s = (int)load_idx(ei, e, is64);                       // src
        int d = (int)load_idx(ei, (long long)N_EDGES + e, is64);  // dst
        if (d >= 0 && d < N_NODES && s >= 0 && s < N_NODES) {
            int p = atomicAdd(&g_cur[d], 1);
            g_csr[p] = s;
        }
    }
}

// ---------------- tiled fp32 GEMM: g_h1[nrows,NO] = X[nrows,K] @ W[K,NO] ----------------
// BM=64 rows/block, BK=64, 256 threads, 4 x (NO/16) micro-tile per thread.
template <int K, int NO, bool EXT>
__global__ void k_gemm(const float* __restrict__ Xext, const float* __restrict__ W,
                       int nrows) {
    constexpr int BM = 64, BK = 64;
    constexpr int TN = NO / 16;  // 4 for NO=64, 2 for NO=32
    __shared__ float xs[BK][BM + 1];  // transposed, padded
    __shared__ float ws[BK][NO];

    const float* X = EXT ? Xext : (const float*)g_h2;
    float* Y = (float*)g_h1;

    const int tid = threadIdx.x;
    const int tr = tid >> 4;   // 0..15 (row group of 4)
    const int tc = tid & 15;   // 0..15 (col group of TN)
    const int row0 = blockIdx.x * BM;

    float acc[4][TN];
#pragma unroll
    for (int i = 0; i < 4; i++)
#pragma unroll
        for (int j = 0; j < TN; j++) acc[i][j] = 0.0f;

    for (int kc = 0; kc < K / BK; kc++) {
#pragma unroll
        for (int t = 0; t < (BM * BK) / 256; t++) {
            int idx = tid + t * 256;
            int r = idx >> 6, k = idx & 63;
            int gr = row0 + r;
            float v = (gr < nrows) ? X[(size_t)gr * K + kc * BK + k] : 0.0f;
            xs[k][r] = v;
        }
#pragma unroll
        for (int t = 0; t < (BK * NO) / 256; t++) {
            int idx = tid + t * 256;
            int k = idx / NO, c = idx % NO;
            ws[k][c] = W[(size_t)(kc * BK + k) * NO + c];
        }
        __syncthreads();

#pragma unroll
        for (int k = 0; k < BK; k++) {
            float xv[4];
#pragma unroll
            for (int i = 0; i < 4; i++) xv[i] = xs[k][tr * 4 + i];
            float wv[TN];
            if (TN == 4) {
                float4 w4 = *reinterpret_cast<const float4*>(&ws[k][tc * 4]);
                wv[0] = w4.x; wv[1] = w4.y; wv[2] = w4.z; wv[3] = w4.w;
            } else {
                float2 w2 = *reinterpret_cast<const float2*>(&ws[k][tc * 2]);
                wv[0] = w2.x; wv[1] = w2.y;
            }
#pragma unroll
            for (int i = 0; i < 4; i++)
#pragma unroll
                for (int j = 0; j < TN; j++) acc[i][j] = fmaf(xv[i], wv[j], acc[i][j]);
        }
        __syncthreads();
    }

#pragma unroll
    for (int i = 0; i < 4; i++) {
        int r = row0 + tr * 4 + i;
        if (r < nrows) {
            if (TN == 4) {
                float4 o = make_float4(acc[i][0], acc[i][1], acc[i][2], acc[i][3]);
                *reinterpret_cast<float4*>(&Y[(size_t)r * NO + tc * 4]) = o;
            } else {
                float2 o = make_float2(acc[i][0], acc[i][1]);
                *reinterpret_cast<float2*>(&Y[(size_t)r * NO + tc * 2]) = o;
            }
        }
    }
}

// ---------------- aggregation ----------------
template <int NO>
__global__ void k_agg(const float* __restrict__ b) {
    int warp = (blockIdx.x * blockDim.x + threadIdx.x) >> 5;
    int lane = threadIdx.x & 31;
    if (warp >= N_NODES) return;
    const float* hin = (const float*)g_h1;
    float* hout = (float*)g_h2;

    int i = warp;
    float di = g_dis[i];
    int start = g_off[i];
    int cnt = g_deg[i];

    float acc0 = 0.0f, acc1 = 0.0f;
    for (int j = 0; j < cnt; j++) {
        int s = g_csr[start + j];
        float fs = g_dis[s];
        const float* hr = hin + (size_t)s * NO;
        acc0 += fs * hr[lane];
        if (NO == 64) acc1 += fs * hr[lane + 32];
    }
    const float* hi = hin + (size_t)i * NO;
    float o0 = di * acc0 + di * di * hi[lane] + b[lane];
    hout[(size_t)i * NO + lane] = fmaxf(o0, 0.0f);
    if (NO == 64) {
        float o1 = di * acc1 + di * di * hi[lane + 32] + b[lane + 32];
        hout[(size_t)i * NO + lane + 32] = fmaxf(o1, 0.0f);
    }
}

// ---------------- pool + classifier (batch sorted) ----------------
__device__ __forceinline__ int lowerb(const void* a, int n, long long key, int is64) {
    int lo = 0, hi = n;
    while (lo < hi) {
        int mid = (lo + hi) >> 1;
        if (load_idx(a, mid, is64) < key) lo = mid + 1; else hi = mid;
    }
    return lo;
}

__global__ void k_pool(const void* __restrict__ batch,
                       const float* __restrict__ Wc1, const float* __restrict__ bc1,
                       const float* __restrict__ Wc2, const float* __restrict__ bc2,
                       float* __restrict__ out) {
    int warp = (blockIdx.x * blockDim.x + threadIdx.x) >> 5;
    int lane = threadIdx.x & 31;
    int wl = (threadIdx.x >> 5);
    if (warp >= N_GRAPHS) return;
    const float* h3 = (const float*)g_h2;
    int is64 = g_is64;

    long long g = warp;
    int start = lowerb(batch, N_NODES, g, is64);
    int end = lowerb(batch, N_NODES, g + 1, is64);

    float acc = 0.0f;
    for (int r = start; r < end; r++) acc += h3[(size_t)r * EMB + lane];
    float cnt = (float)(end - start);
    float emb = acc / fmaxf(cnt, 1.0f);

    __shared__ float sh[8][EMB];
    sh[wl][lane] = emb;
    __syncwarp();

    float partial = 0.0f;
    if (lane < 16) {
        float t = bc1[lane];
#pragma unroll
        for (int c = 0; c < EMB; c++) t = fmaf(sh[wl][c], Wc1[c * 16 + lane], t);
        t = fmaxf(t, 0.0f);
        partial = t * Wc2[lane];
    }
#pragma unroll
    for (int o = 8; o > 0; o >>= 1) partial += __shfl_down_sync(0xffffffffu, partial, o);
    if (lane == 0) out[g] = partial + bc2[0];
}

// ---------------- launch ----------------
extern "C" void kernel_launch(void* const* d_in, const int* in_sizes, int n_in,
                              void* d_out, int out_size) {
    const float* x     = (const float*)d_in[0];
    const void*  ei    = d_in[1];
    const void*  batch = d_in[2];
    const float* W1 = (const float*)d_in[3];  const float* b1 = (const float*)d_in[4];
    const float* W2 = (const float*)d_in[5];  const float* b2 = (const float*)d_in[6];
    const float* W3 = (const float*)d_in[7];  const float* b3 = (const float*)d_in[8];
    const float* Wc1 = (const float*)d_in[9]; const float* bc1 = (const float*)d_in[10];
    const float* Wc2 = (const float*)d_in[11]; const float* bc2 = (const float*)d_in[12];
    float* out = (float*)d_out;

    const int NB_N1024 = (N_NODES + 1023) / 1024;   // 196
    const int NB_E256  = (N_EDGES + 255) / 256;     // 4883
    const int NB_N256  = (N_NODES + 255) / 256;

    // dtype detection + preprocessing: degree -> dis, CSR
    k_detect<<<1, 128>>>((const unsigned*)ei);
    k_zero_deg<<<NB_N1024, 1024>>>();
    k_count_deg<<<NB_E256, 256>>>(ei);
    k_scan1<<<NB_N1024, 1024>>>();
    k_scan2<<<1, 256>>>(NB_N1024);
    k_scan3<<<NB_N256, 256>>>();
    k_fill_csr<<<NB_E256, 256>>>(ei);

    const int GEMM_BLKS = N_NODES / 64;                 // 3125 (exact)
    const int AGG_BLKS  = (N_NODES * 32 + 255) / 256;   // 25000

    // layer 1: 128 -> 64  (x -> g_h1 -> g_h2)
    k_gemm<128, 64, true><<<GEMM_BLKS, 256>>>(x, W1, N_NODES);
    k_agg<64><<<AGG_BLKS, 256>>>(b1);
    // layer 2: 64 -> 64   (g_h2 -> g_h1 -> g_h2)
    k_gemm<64, 64, false><<<GEMM_BLKS, 256>>>(nullptr, W2, N_NODES);
    k_agg<64><<<AGG_BLKS, 256>>>(b2);
    // layer 3: 64 -> 32   (g_h2 -> g_h1 -> g_h2)
    k_gemm<64, 32, false><<<GEMM_BLKS, 256>>>(nullptr, W3, N_NODES);
    k_agg<32><<<AGG_BLKS, 256>>>(b3);

    // pool + classifier
    k_pool<<<N_GRAPHS / 8, 256>>>(batch, Wc1, bc1, Wc2, bc2, out);
}

// round 4
// speedup vs baseline: 1.2098x; 1.2098x over previous
#include <cuda_runtime.h>
#include <math.h>

#define N_NODES 200000
#define N_EDGES 1250000
#define N_GRAPHS 2048
#define IN_CH 128
#define HID 64
#define EMB 32

// ---------------- scratch (static device globals; no allocation) ----------------
__device__ int   g_is64;                 // 1 if edge_index/batch are int64, else int32
__device__ int   g_deg[N_NODES];
__device__ float g_dis[N_NODES];
__device__ int   g_off[N_NODES];
__device__ int   g_cur[N_NODES];
__device__ int   g_csr[N_EDGES];
__device__ int   g_bsums[256];
__device__ __align__(16) float g_h1[(size_t)N_NODES * 64];   // GEMM output
__device__ __align__(16) float g_h2[(size_t)N_NODES * 64];   // AGG output / GEMM input

__device__ __forceinline__ long long load_idx(const void* p, long long i, int is64) {
    if (is64) return ((const long long*)p)[i];
    return (long long)((const int*)p)[i];
}

// ---------------- dtype detector ----------------
__global__ void k_detect(const unsigned* __restrict__ ei_words) {
    __shared__ int any_nonzero;
    if (threadIdx.x == 0) any_nonzero = 0;
    __syncthreads();
    unsigned w = ei_words[2 * threadIdx.x + 1];
    if (w != 0u) atomicOr(&any_nonzero, 1);
    __syncthreads();
    if (threadIdx.x == 0) g_is64 = any_nonzero ? 0 : 1;
}

// ---------------- utility: block inclusive scan ----------------
template <int NT>
__device__ __forceinline__ int block_inclusive_scan(int v, int tid) {
    int lane = tid & 31, w = tid >> 5;
    int x = v;
#pragma unroll
    for (int o = 1; o < 32; o <<= 1) {
        int y = __shfl_up_sync(0xffffffffu, x, o);
        if (lane >= o) x += y;
    }
    __shared__ int wsum[NT / 32];
    if (lane == 31) wsum[w] = x;
    __syncthreads();
    if (w == 0) {
        const int NW = NT / 32;
        int s = (lane < NW) ? wsum[lane] : 0;
#pragma unroll
        for (int o = 1; o < 32; o <<= 1) {
            int y = __shfl_up_sync(0xffffffffu, s, o);
            if (lane >= o) s += y;
        }
        if (lane < NW) wsum[lane] = s;
    }
    __syncthreads();
    return x + (w ? wsum[w - 1] : 0);
}

// ---------------- graph preprocessing ----------------
__global__ void k_zero_deg() {
    int i = blockIdx.x * 1024 + threadIdx.x;
    if (i < N_NODES) g_deg[i] = 0;
}

__global__ void k_count_deg(const void* __restrict__ ei) {
    int e = blockIdx.x * 256 + threadIdx.x;
    int is64 = g_is64;
    if (e < N_EDGES) {
        int d = (int)load_idx(ei, (long long)N_EDGES + e, is64);
        if (d >= 0 && d < N_NODES) atomicAdd(&g_deg[d], 1);
    }
}

__global__ void k_scan1() {
    int idx = blockIdx.x * 1024 + threadIdx.x;
    int v = (idx < N_NODES) ? g_deg[idx] : 0;
    int incl = block_inclusive_scan<1024>(v, threadIdx.x);
    if (idx < N_NODES) g_off[idx] = incl - v;
    if (threadIdx.x == 1023) g_bsums[blockIdx.x] = incl;
}

__global__ void k_scan2(int nb) {
    int v = ((int)threadIdx.x < nb) ? g_bsums[threadIdx.x] : 0;
    int incl = block_inclusive_scan<256>(v, threadIdx.x);
    if ((int)threadIdx.x < nb) g_bsums[threadIdx.x] = incl - v;
}

__global__ void k_scan3() {
    int idx = blockIdx.x * 256 + threadIdx.x;
    if (idx < N_NODES) {
        int o = g_off[idx] + g_bsums[idx >> 10];
        g_off[idx] = o;
        g_cur[idx] = o;
        g_dis[idx] = rsqrtf(1.0f + (float)g_deg[idx]);
    }
}

__global__ void k_fill_csr(const void* __restrict__ ei) {
    int e = blockIdx.x * 256 + threadIdx.x;
    int is64 = g_is64;
    if (e < N_EDGES) {
        int s = (int)load_idx(ei, e, is64);
        int d = (int)load_idx(ei, (long long)N_EDGES + e, is64);
        if (d >= 0 && d < N_NODES && s >= 0 && s < N_NODES) {
            int p = atomicAdd(&g_cur[d], 1);
            g_csr[p] = s;
        }
    }
}

// ---------------- tiled fp32 GEMM: g_h1[nrows,NO] = X[nrows,K] @ W[K,NO] ----------------
// BM=128 rows/block, BK=64, 256 threads, 8 x (NO/16) micro-tile per thread.
// smem: xs[64][128] (32KB, transposed, conflict-free) + ws[64][NO] (<=16KB) = <=48KB.
template <int K, int NO, bool EXT>
__global__ void __launch_bounds__(256) k_gemm(const float* __restrict__ Xext,
                                              const float* __restrict__ W, int nrows) {
    constexpr int BM = 128, BK = 64;
    constexpr int TN = NO / 16;  // 4 for NO=64, 2 for NO=32
    constexpr int NKC = K / BK;
    __shared__ float xs[BK][BM];
    __shared__ float ws[BK][NO];

    const float* X = EXT ? Xext : (const float*)g_h2;
    float* Y = (float*)g_h1;

    const int tid = threadIdx.x;
    const int tr = tid >> 4;   // 0..15: rows tr*8 .. tr*8+7
    const int tc = tid & 15;   // 0..15: cols tc*TN ..
    const int row0 = blockIdx.x * BM;

    // X-load mapping: thread handles row (tid&127), column-half (tid>>7)
    const int lr = tid & 127;
    const int lhalf = tid >> 7;
    const int gr_load = row0 + lr;
    const bool ld_ok = (gr_load < nrows);
    const float4* Xr = (const float4*)(X + (size_t)gr_load * K);

    float acc[8][TN];
#pragma unroll
    for (int i = 0; i < 8; i++)
#pragma unroll
        for (int j = 0; j < TN; j++) acc[i][j] = 0.0f;

#pragma unroll
    for (int kc = 0; kc < NKC; kc++) {
        if (kc > 0) __syncthreads();
        // load X chunk [BM x BK] transposed into xs
#pragma unroll
        for (int t = 0; t < 8; t++) {
            int c4 = lhalf * 8 + t;                       // float4 index within chunk (0..15)
            float4 v = ld_ok ? Xr[kc * (BK / 4) + c4] : make_float4(0.f, 0.f, 0.f, 0.f);
            int k0 = c4 * 4;
            xs[k0 + 0][lr] = v.x; xs[k0 + 1][lr] = v.y;
            xs[k0 + 2][lr] = v.z; xs[k0 + 3][lr] = v.w;
        }
        // load W chunk [BK x NO]
        {
            const float4* W4 = (const float4*)(W + (size_t)kc * BK * NO);
            float4* ws4 = (float4*)ws;
#pragma unroll
            for (int t = tid; t < BK * NO / 4; t += 256) ws4[t] = W4[t];
        }
        __syncthreads();

#pragma unroll 8
        for (int k = 0; k < BK; k++) {
            float xv[8];
            *(float4*)&xv[0] = *(const float4*)&xs[k][tr * 8];
            *(float4*)&xv[4] = *(const float4*)&xs[k][tr * 8 + 4];
            float wv[TN];
            if (TN == 4) {
                *(float4*)&wv[0] = *(const float4*)&ws[k][tc * 4];
            } else {
                *(float2*)&wv[0] = *(const float2*)&ws[k][tc * 2];
            }
#pragma unroll
            for (int i = 0; i < 8; i++)
#pragma unroll
                for (int j = 0; j < TN; j++) acc[i][j] = fmaf(xv[i], wv[j], acc[i][j]);
        }
    }

#pragma unroll
    for (int i = 0; i < 8; i++) {
        int r = row0 + tr * 8 + i;
        if (r < nrows) {
            if (TN == 4) {
                float4 o = make_float4(acc[i][0], acc[i][1], acc[i][2], acc[i][3]);
                *reinterpret_cast<float4*>(&Y[(size_t)r * NO + tc * 4]) = o;
            } else {
                float2 o = make_float2(acc[i][0], acc[i][1]);
                *reinterpret_cast<float2*>(&Y[(size_t)r * NO + tc * 2]) = o;
            }
        }
    }
}

// ---------------- aggregation: g_h2[i] = relu(di*sum_j dis[s]*h[s] + di^2*h[i] + b) ----------------
template <int NO>
__global__ void k_agg(const float* __restrict__ b) {
    int warp = (blockIdx.x * blockDim.x + threadIdx.x) >> 5;
    int lane = threadIdx.x & 31;
    if (warp >= N_NODES) return;
    const float* hin = (const float*)g_h1;
    float* hout = (float*)g_h2;

    int i = warp;
    float di = g_dis[i];
    int start = g_off[i];
    int cnt = g_deg[i];

    float a0 = 0.f, a1 = 0.f, b0 = 0.f, b1 = 0.f;
    int j = 0;
    for (; j + 2 <= cnt; j += 2) {
        int s0 = g_csr[start + j];
        int s1 = g_csr[start + j + 1];
        float f0 = g_dis[s0];
        float f1 = g_dis[s1];
        const float* h0 = hin + (size_t)s0 * NO;
        const float* h1p = hin + (size_t)s1 * NO;
        a0 += f0 * h0[lane];
        b0 += f1 * h1p[lane];
        if (NO == 64) {
            a1 += f0 * h0[lane + 32];
            b1 += f1 * h1p[lane + 32];
        }
    }
    if (j < cnt) {
        int s0 = g_csr[start + j];
        float f0 = g_dis[s0];
        const float* h0 = hin + (size_t)s0 * NO;
        a0 += f0 * h0[lane];
        if (NO == 64) a1 += f0 * h0[lane + 32];
    }
    a0 += b0; a1 += b1;

    const float* hi = hin + (size_t)i * NO;
    float o0 = di * a0 + di * di * hi[lane] + b[lane];
    hout[(size_t)i * NO + lane] = fmaxf(o0, 0.0f);
    if (NO == 64) {
        float o1 = di * a1 + di * di * hi[lane + 32] + b[lane + 32];
        hout[(size_t)i * NO + lane + 32] = fmaxf(o1, 0.0f);
    }
}

// ---------------- pool + classifier (batch sorted) ----------------
__device__ __forceinline__ int lowerb(const void* a, int n, long long key, int is64) {
    int lo = 0, hi = n;
    while (lo < hi) {
        int mid = (lo + hi) >> 1;
        if (load_idx(a, mid, is64) < key) lo = mid + 1; else hi = mid;
    }
    return lo;
}

__global__ void k_pool(const void* __restrict__ batch,
                       const float* __restrict__ Wc1, const float* __restrict__ bc1,
                       const float* __restrict__ Wc2, const float* __restrict__ bc2,
                       float* __restrict__ out) {
    int warp = (blockIdx.x * blockDim.x + threadIdx.x) >> 5;
    int lane = threadIdx.x & 31;
    int wl = (threadIdx.x >> 5);
    if (warp >= N_GRAPHS) return;
    const float* h3 = (const float*)g_h2;
    int is64 = g_is64;

    long long g = warp;
    int start = lowerb(batch, N_NODES, g, is64);
    int end = lowerb(batch, N_NODES, g + 1, is64);

    float acc = 0.0f;
    for (int r = start; r < end; r++) acc += h3[(size_t)r * EMB + lane];
    float cnt = (float)(end - start);
    float emb = acc / fmaxf(cnt, 1.0f);

    __shared__ float sh[8][EMB];
    sh[wl][lane] = emb;
    __syncwarp();

    float partial = 0.0f;
    if (lane < 16) {
        float t = bc1[lane];
#pragma unroll
        for (int c = 0; c < EMB; c++) t = fmaf(sh[wl][c], Wc1[c * 16 + lane], t);
        t = fmaxf(t, 0.0f);
        partial = t * Wc2[lane];
    }
#pragma unroll
    for (int o = 8; o > 0; o >>= 1) partial += __shfl_down_sync(0xffffffffu, partial, o);
    if (lane == 0) out[g] = partial + bc2[0];
}

// ---------------- launch ----------------
extern "C" void kernel_launch(void* const* d_in, const int* in_sizes, int n_in,
                              void* d_out, int out_size) {
    const float* x     = (const float*)d_in[0];
    const void*  ei    = d_in[1];
    const void*  batch = d_in[2];
    const float* W1 = (const float*)d_in[3];  const float* b1 = (const float*)d_in[4];
    const float* W2 = (const float*)d_in[5];  const float* b2 = (const float*)d_in[6];
    const float* W3 = (const float*)d_in[7];  const float* b3 = (const float*)d_in[8];
    const float* Wc1 = (const float*)d_in[9]; const float* bc1 = (const float*)d_in[10];
    const float* Wc2 = (const float*)d_in[11]; const float* bc2 = (const float*)d_in[12];
    float* out = (float*)d_out;

    const int NB_N1024 = (N_NODES + 1023) / 1024;   // 196
    const int NB_E256  = (N_EDGES + 255) / 256;     // 4883
    const int NB_N256  = (N_NODES + 255) / 256;

    k_detect<<<1, 128>>>((const unsigned*)ei);
    k_zero_deg<<<NB_N1024, 1024>>>();
    k_count_deg<<<NB_E256, 256>>>(ei);
    k_scan1<<<NB_N1024, 1024>>>();
    k_scan2<<<1, 256>>>(NB_N1024);
    k_scan3<<<NB_N256, 256>>>();
    k_fill_csr<<<NB_E256, 256>>>(ei);

    const int GEMM_BLKS = (N_NODES + 127) / 128;        // 1563
    const int AGG_BLKS  = (N_NODES * 32 + 255) / 256;   // 25000

    // layer 1: 128 -> 64  (x -> g_h1 -> g_h2)
    k_gemm<128, 64, true><<<GEMM_BLKS, 256>>>(x, W1, N_NODES);
    k_agg<64><<<AGG_BLKS, 256>>>(b1);
    // layer 2: 64 -> 64   (g_h2 -> g_h1 -> g_h2)
    k_gemm<64, 64, false><<<GEMM_BLKS, 256>>>(nullptr, W2, N_NODES);
    k_agg<64><<<AGG_BLKS, 256>>>(b2);
    // layer 3: 64 -> 32   (g_h2 -> g_h1 -> g_h2)
    k_gemm<64, 32, false><<<GEMM_BLKS, 256>>>(nullptr, W3, N_NODES);
    k_agg<32><<<AGG_BLKS, 256>>>(b3);

    // pool + classifier
    k_pool<<<N_GRAPHS / 8, 256>>>(batch, Wc1, bc1, Wc2, bc2, out);
}